// round 1
// baseline (speedup 1.0000x reference)
#include <cuda_runtime.h>
#include <math.h>

// FlashAttention forward, causal, fp32.
// Shapes: q,k,v,out = [B=1, S=4096, H=16, D=64], layout: d contiguous,
// h stride 64, s stride H*D=1024.
//
// One CTA handles one (head, 128-query-row) tile. 128 threads, one query
// row per thread (q row + output accumulator in registers). K/V streamed
// through shared memory in 32-row tiles. Online softmax (base-2).

constexpr int S  = 4096;
constexpr int H  = 16;
constexpr int Dh = 64;
constexpr int BM = 128;   // query rows per CTA
constexpr int BN = 32;    // k/v rows per smem tile
constexpr int NTHREADS = 128;

__global__ void __launch_bounds__(NTHREADS, 2)
fa_fwd_kernel(const float* __restrict__ q,
              const float* __restrict__ k,
              const float* __restrict__ v,
              const int*   __restrict__ causal_p,
              float*       __restrict__ out)
{
    __shared__ float Ks[BN * Dh];                 // 8 KB
    __shared__ float Vs[BN * Dh];                 // 8 KB
    __shared__ float Ss[NTHREADS * (BN + 1)];     // 16.5 KB, padded stride 33

    const int h  = blockIdx.x;
    // Launch the heaviest q-tiles first (largest causal extent) to shrink tail.
    const int qb = (int)(gridDim.y - 1) - (int)blockIdx.y;
    const int t  = threadIdx.x;
    const int q_row = qb * BM + t;
    const int causal = *causal_p;

    // scale = D^-0.5, folded with log2(e) so we can use exp2f (MUFU.EX2).
    const float scale = 0.125f * 1.44269504088896340736f;

    // Load this thread's q row into registers (16x LDG.128).
    float qr[Dh];
    {
        const float4* qsrc =
            (const float4*)(q + (size_t)q_row * (H * Dh) + h * Dh);
        #pragma unroll
        for (int i = 0; i < Dh / 4; i++) {
            float4 f = qsrc[i];
            qr[4*i+0] = f.x; qr[4*i+1] = f.y;
            qr[4*i+2] = f.z; qr[4*i+3] = f.w;
        }
    }

    float m = -INFINITY;
    float l = 0.0f;
    float acc[Dh];
    #pragma unroll
    for (int d = 0; d < Dh; d++) acc[d] = 0.0f;

    const int ktiles = causal ? ((qb + 1) * (BM / BN)) : (S / BN);
    float* myS = &Ss[t * (BN + 1)];

    for (int kb = 0; kb < ktiles; kb++) {
        const int k0 = kb * BN;

        __syncthreads();  // previous tile fully consumed before overwrite
        // Cooperative K/V tile load: BN*Dh/4 = 512 float4 each; 4 per thread.
        #pragma unroll
        for (int i = 0; i < (BN * Dh / 4) / NTHREADS; i++) {
            int idx = t + i * NTHREADS;          // float4 index within tile
            int row = idx >> 4;                  // Dh/4 = 16 float4 per row
            int c4  = idx & 15;
            size_t goff = (size_t)(k0 + row) * (H * Dh) + (size_t)h * Dh;
            ((float4*)Ks)[idx] = ((const float4*)(k + goff))[c4];
            ((float4*)Vs)[idx] = ((const float4*)(v + goff))[c4];
        }
        __syncthreads();

        // Pass A: scores s_j = scale * <q_row, K_j>, causal mask, tile max.
        float tmax = -INFINITY;
        for (int j = 0; j < BN; j++) {
            const float4* K4 = (const float4*)(Ks + j * Dh);
            float s = 0.0f;
            #pragma unroll
            for (int d4 = 0; d4 < Dh / 4; d4++) {
                float4 kf = K4[d4];   // broadcast across lanes
                s = fmaf(qr[4*d4+0], kf.x, s);
                s = fmaf(qr[4*d4+1], kf.y, s);
                s = fmaf(qr[4*d4+2], kf.z, s);
                s = fmaf(qr[4*d4+3], kf.w, s);
            }
            s *= scale;
            if (causal && (k0 + j > q_row)) s = -INFINITY;
            myS[j] = s;
            tmax = fmaxf(tmax, s);
        }

        // Online softmax rescale. First tile: m=-inf, newm finite (diag
        // element always unmasked) -> corr = exp2(-inf) = 0. Fully-masked
        // late tiles: tmax=-inf, newm=m finite -> corr=1, all e=0.
        float newm = fmaxf(m, tmax);
        float corr = exp2f(m - newm);
        m = newm;
        l *= corr;
        #pragma unroll
        for (int d = 0; d < Dh; d++) acc[d] *= corr;

        // Pass B: exponentiate + accumulate P*V.
        for (int j = 0; j < BN; j++) {
            float e = exp2f(myS[j] - newm);
            l += e;
            const float4* V4 = (const float4*)(Vs + j * Dh);
            #pragma unroll
            for (int d4 = 0; d4 < Dh / 4; d4++) {
                float4 vf = V4[d4];   // broadcast across lanes
                acc[4*d4+0] = fmaf(e, vf.x, acc[4*d4+0]);
                acc[4*d4+1] = fmaf(e, vf.y, acc[4*d4+1]);
                acc[4*d4+2] = fmaf(e, vf.z, acc[4*d4+2]);
                acc[4*d4+3] = fmaf(e, vf.w, acc[4*d4+3]);
            }
        }
    }

    const float inv = 1.0f / l;
    float4* dst = (float4*)(out + (size_t)q_row * (H * Dh) + (size_t)h * Dh);
    #pragma unroll
    for (int i = 0; i < Dh / 4; i++) {
        float4 f;
        f.x = acc[4*i+0] * inv;
        f.y = acc[4*i+1] * inv;
        f.z = acc[4*i+2] * inv;
        f.w = acc[4*i+3] * inv;
        dst[i] = f;
    }
}

extern "C" void kernel_launch(void* const* d_in, const int* in_sizes, int n_in,
                              void* d_out, int out_size)
{
    const float* q = (const float*)d_in[0];
    const float* k = (const float*)d_in[1];
    const float* v = (const float*)d_in[2];
    const int* causal = (const int*)d_in[3];
    float* out = (float*)d_out;

    dim3 grid(H, S / BM);   // (16, 32) = 512 CTAs
    fa_fwd_kernel<<<grid, NTHREADS>>>(q, k, v, causal, out);
}

// round 3
// speedup vs baseline: 5.3774x; 5.3774x over previous
#include <cuda_runtime.h>
#include <math.h>
#include <stdint.h>

// FlashAttention fwd, causal, fp32 I/O, tf32 mma.sync (tensor pipe), sm_103.
// B=1, S=4096, H=16, D=64. Layout [s, h, d]: d contiguous, s stride H*D=1024.
//
// CTA = (head, 128 q rows), 4 warps x 32 rows. KV tile BN=64 streamed via smem.
// mma.sync.aligned.m16n8k8.row.col.f32.tf32.tf32.f32 throughout.

constexpr int S_LEN = 4096;
constexpr int H     = 16;
constexpr int Dh    = 64;
constexpr int BM    = 128;
constexpr int BN    = 64;
constexpr int NT    = 128;
constexpr int PAD   = 68;    // floats per smem row: conflict-free fragment access

constexpr int KS_OFF = 0;
constexpr int VS_OFF = BN * PAD;          // K tile: 64 rows
constexpr int PS_OFF = 2 * BN * PAD;      // P / Q-staging: 128 rows
constexpr int SMEM_BYTES = (PS_OFF + BM * PAD) * 4;   // 69632 B

__device__ __forceinline__ uint32_t f2tf32(float f) {
    uint32_t r;
    asm("cvt.rna.tf32.f32 %0, %1;" : "=r"(r) : "f"(f));
    return r;
}
__device__ __forceinline__ float ex2(float x) {
    float y;
    asm("ex2.approx.f32 %0, %1;" : "=f"(y) : "f"(x));
    return y;
}
__device__ __forceinline__ void mma8(float* d, const uint32_t* a, const uint32_t* b) {
    asm volatile(
        "mma.sync.aligned.m16n8k8.row.col.f32.tf32.tf32.f32 "
        "{%0,%1,%2,%3}, {%4,%5,%6,%7}, {%8,%9}, {%0,%1,%2,%3};"
        : "+f"(d[0]), "+f"(d[1]), "+f"(d[2]), "+f"(d[3])
        : "r"(a[0]), "r"(a[1]), "r"(a[2]), "r"(a[3]), "r"(b[0]), "r"(b[1]));
}

__global__ void __launch_bounds__(NT, 2)
fa_mma_kernel(const float* __restrict__ q, const float* __restrict__ k,
              const float* __restrict__ v, const int* __restrict__ causal_p,
              float* __restrict__ out)
{
    extern __shared__ float sm[];
    float* Ks = sm + KS_OFF;
    float* Vs = sm + VS_OFF;
    float* Ps = sm + PS_OFF;

    const int t    = threadIdx.x;
    const int wid  = t >> 5;
    const int lane = t & 31;
    const int g    = lane >> 2;    // groupID   (0..7)
    const int tg   = lane & 3;     // thread-in-group (0..3)
    const int h    = blockIdx.x;
    const int qb   = (int)gridDim.y - 1 - (int)blockIdx.y;  // heavy tiles first
    const int causal = *causal_p;
    const int wb   = wid * 32;     // warp's row base within CTA tile
    const float c  = 0.125f * 1.44269504088896340736f;      // D^-0.5 * log2(e)

    // ---- stage Q (scale folded, tf32) into Ps, then lift fragments to regs
    #pragma unroll
    for (int i = 0; i < 16; i++) {
        int idx = t + i * NT, row = idx >> 4, c4 = idx & 15;
        float4 f = ((const float4*)(q + (size_t)(qb * BM + row) * (H * Dh) + h * Dh))[c4];
        uint32_t* d = (uint32_t*)(Ps + row * PAD + c4 * 4);
        d[0] = f2tf32(f.x * c); d[1] = f2tf32(f.y * c);
        d[2] = f2tf32(f.z * c); d[3] = f2tf32(f.w * c);
    }
    __syncthreads();

    uint32_t qa[2][8][4];   // [mtile][ktile][frag]
    #pragma unroll
    for (int mt = 0; mt < 2; mt++) {
        int r0 = wb + mt * 16 + g;
        #pragma unroll
        for (int kt = 0; kt < 8; kt++) {
            qa[mt][kt][0] = __float_as_uint(Ps[r0 * PAD + kt * 8 + tg]);
            qa[mt][kt][1] = __float_as_uint(Ps[(r0 + 8) * PAD + kt * 8 + tg]);
            qa[mt][kt][2] = __float_as_uint(Ps[r0 * PAD + kt * 8 + tg + 4]);
            qa[mt][kt][3] = __float_as_uint(Ps[(r0 + 8) * PAD + kt * 8 + tg + 4]);
        }
    }
    // loop-top __syncthreads protects Ps before the first P store.

    float o[2][8][4];
    #pragma unroll
    for (int mt = 0; mt < 2; mt++)
        #pragma unroll
        for (int nt = 0; nt < 8; nt++)
            #pragma unroll
            for (int e = 0; e < 4; e++) o[mt][nt][e] = 0.0f;
    float mrow[4] = {-INFINITY, -INFINITY, -INFINITY, -INFINITY};
    float lrow[4] = {0.0f, 0.0f, 0.0f, 0.0f};

    const int ktiles = causal ? 2 * (qb + 1) : (S_LEN / BN);

    for (int kb = 0; kb < ktiles; kb++) {
        const int k0 = kb * BN;

        __syncthreads();   // prev tile fully consumed (Ks/Vs/Ps reads done)
        // ---- K/V tile -> smem (tf32). 8 float4 per thread each.
        #pragma unroll
        for (int i = 0; i < 8; i++) {
            int idx = t + i * NT, row = idx >> 4, c4 = idx & 15;
            size_t go = (size_t)(k0 + row) * (H * Dh) + (size_t)h * Dh;
            float4 fk = ((const float4*)(k + go))[c4];
            uint32_t* dk = (uint32_t*)(Ks + row * PAD + c4 * 4);
            dk[0] = f2tf32(fk.x); dk[1] = f2tf32(fk.y);
            dk[2] = f2tf32(fk.z); dk[3] = f2tf32(fk.w);
            float4 fv = ((const float4*)(v + go))[c4];
            uint32_t* dv = (uint32_t*)(Vs + row * PAD + c4 * 4);
            dv[0] = f2tf32(fv.x); dv[1] = f2tf32(fv.y);
            dv[2] = f2tf32(fv.z); dv[3] = f2tf32(fv.w);
        }
        __syncthreads();

        // ---- MMA1: S[32 x 64] = Q @ K^T (per warp)
        float s[2][8][4];
        #pragma unroll
        for (int mt = 0; mt < 2; mt++)
            #pragma unroll
            for (int nt = 0; nt < 8; nt++)
                #pragma unroll
                for (int e = 0; e < 4; e++) s[mt][nt][e] = 0.0f;

        #pragma unroll
        for (int kt = 0; kt < 8; kt++) {
            #pragma unroll
            for (int nt = 0; nt < 8; nt++) {
                uint32_t b[2];
                b[0] = __float_as_uint(Ks[(nt * 8 + g) * PAD + kt * 8 + tg]);
                b[1] = __float_as_uint(Ks[(nt * 8 + g) * PAD + kt * 8 + tg + 4]);
                mma8(s[0][nt], qa[0][kt], b);
                mma8(s[1][nt], qa[1][kt], b);
            }
        }

        // ---- causal mask (only the two diagonal tiles need it)
        if (causal && kb >= 2 * qb) {
            #pragma unroll
            for (int mt = 0; mt < 2; mt++) {
                int r0 = qb * BM + wb + mt * 16 + g;
                #pragma unroll
                for (int nt = 0; nt < 8; nt++) {
                    int col = k0 + nt * 8 + 2 * tg;
                    if (col     > r0)     s[mt][nt][0] = -INFINITY;
                    if (col + 1 > r0)     s[mt][nt][1] = -INFINITY;
                    if (col     > r0 + 8) s[mt][nt][2] = -INFINITY;
                    if (col + 1 > r0 + 8) s[mt][nt][3] = -INFINITY;
                }
            }
        }

        // ---- online softmax (4 rows per thread: mt*2+hi; quad holds a row)
        #pragma unroll
        for (int mt = 0; mt < 2; mt++) {
            #pragma unroll
            for (int hi = 0; hi < 2; hi++) {
                const int ri = mt * 2 + hi;
                float tm = -INFINITY;
                #pragma unroll
                for (int nt = 0; nt < 8; nt++)
                    tm = fmaxf(tm, fmaxf(s[mt][nt][hi * 2], s[mt][nt][hi * 2 + 1]));
                tm = fmaxf(tm, __shfl_xor_sync(0xffffffffu, tm, 1));
                tm = fmaxf(tm, __shfl_xor_sync(0xffffffffu, tm, 2));
                float nm   = fmaxf(mrow[ri], tm);
                float corr = ex2(mrow[ri] - nm);     // -inf first tile -> 0
                mrow[ri] = nm;
                float ls = 0.0f;
                #pragma unroll
                for (int nt = 0; nt < 8; nt++) {
                    float e0 = ex2(s[mt][nt][hi * 2]     - nm);
                    float e1 = ex2(s[mt][nt][hi * 2 + 1] - nm);
                    s[mt][nt][hi * 2]     = e0;
                    s[mt][nt][hi * 2 + 1] = e1;
                    ls += e0 + e1;
                    o[mt][nt][hi * 2]     *= corr;
                    o[mt][nt][hi * 2 + 1] *= corr;
                }
                lrow[ri] = lrow[ri] * corr + ls;
            }
        }

        // ---- P (tf32) -> smem in row-major; warp-private rows, so warp sync only
        #pragma unroll
        for (int mt = 0; mt < 2; mt++) {
            int r0 = wb + mt * 16 + g;
            #pragma unroll
            for (int nt = 0; nt < 8; nt++) {
                uint32_t* d0 = (uint32_t*)(Ps + r0 * PAD + nt * 8 + 2 * tg);
                d0[0] = f2tf32(s[mt][nt][0]); d0[1] = f2tf32(s[mt][nt][1]);
                uint32_t* d1 = (uint32_t*)(Ps + (r0 + 8) * PAD + nt * 8 + 2 * tg);
                d1[0] = f2tf32(s[mt][nt][2]); d1[1] = f2tf32(s[mt][nt][3]);
            }
        }
        __syncwarp();

        // ---- MMA2: O += P @ V
        #pragma unroll
        for (int kt = 0; kt < 8; kt++) {
            uint32_t pa[2][4];
            #pragma unroll
            for (int mt = 0; mt < 2; mt++) {
                int r0 = wb + mt * 16 + g;
                pa[mt][0] = __float_as_uint(Ps[r0 * PAD + kt * 8 + tg]);
                pa[mt][1] = __float_as_uint(Ps[(r0 + 8) * PAD + kt * 8 + tg]);
                pa[mt][2] = __float_as_uint(Ps[r0 * PAD + kt * 8 + tg + 4]);
                pa[mt][3] = __float_as_uint(Ps[(r0 + 8) * PAD + kt * 8 + tg + 4]);
            }
            #pragma unroll
            for (int nt = 0; nt < 8; nt++) {
                uint32_t b[2];
                b[0] = __float_as_uint(Vs[(kt * 8 + tg) * PAD + nt * 8 + g]);
                b[1] = __float_as_uint(Vs[(kt * 8 + tg + 4) * PAD + nt * 8 + g]);
                mma8(o[0][nt], pa[0], b);
                mma8(o[1][nt], pa[1], b);
            }
        }
    }

    // ---- finalize: full row-sum across the quad, normalize, store
    #pragma unroll
    for (int ri = 0; ri < 4; ri++) {
        lrow[ri] += __shfl_xor_sync(0xffffffffu, lrow[ri], 1);
        lrow[ri] += __shfl_xor_sync(0xffffffffu, lrow[ri], 2);
    }
    #pragma unroll
    for (int mt = 0; mt < 2; mt++) {
        #pragma unroll
        for (int hi = 0; hi < 2; hi++) {
            const int ri = mt * 2 + hi;
            const float inv = 1.0f / lrow[ri];
            const int rg = qb * BM + wb + mt * 16 + g + hi * 8;
            float* op = out + (size_t)rg * (H * Dh) + (size_t)h * Dh;
            #pragma unroll
            for (int nt = 0; nt < 8; nt++) {
                float2 f2;
                f2.x = o[mt][nt][hi * 2]     * inv;
                f2.y = o[mt][nt][hi * 2 + 1] * inv;
                *(float2*)(op + nt * 8 + 2 * tg) = f2;
            }
        }
    }
}

extern "C" void kernel_launch(void* const* d_in, const int* in_sizes, int n_in,
                              void* d_out, int out_size)
{
    const float* q = (const float*)d_in[0];
    const float* k = (const float*)d_in[1];
    const float* v = (const float*)d_in[2];
    const int* causal = (const int*)d_in[3];
    float* out = (float*)d_out;

    cudaFuncSetAttribute(fa_mma_kernel,
                         cudaFuncAttributeMaxDynamicSharedMemorySize, SMEM_BYTES);
    dim3 grid(H, S_LEN / BM);   // (16, 32)
    fa_mma_kernel<<<grid, NT, SMEM_BYTES>>>(q, k, v, causal, out);
}

// round 4
// speedup vs baseline: 5.9458x; 1.1057x over previous
#include <cuda_runtime.h>
#include <math.h>
#include <stdint.h>

// FlashAttention fwd, causal, fp32 I/O, tf32 mma.sync, cp.async pipelined.
// B=1, S=4096, H=16, D=64. Layout [s, h, d]: d contiguous, s stride H*D=1024.
//
// CTA = (head, 128 q rows), 4 warps x 32 rows. BN=64 kv tile, double-buffered
// via cp.async.cg (raw fp32; tensor core truncates to tf32 — Q is rna-rounded).

constexpr int S_LEN = 4096;
constexpr int H     = 16;
constexpr int Dh    = 64;
constexpr int BM    = 128;
constexpr int BN    = 64;
constexpr int NT    = 128;
constexpr int PAD   = 68;    // floats/row: scalar frag LDS conflict-free (4g+tg)

constexpr int TILE_F = BN * PAD;              // 4352 floats per K or V buffer
// layout: K0 | K1 | V0 | V1 | Ps
constexpr int K0_OFF = 0;
constexpr int V0_OFF = 2 * TILE_F;
constexpr int PS_OFF = 4 * TILE_F;
constexpr int SMEM_BYTES = (PS_OFF + BM * PAD) * 4;   // 104448 B -> 2 CTAs/SM

__device__ __forceinline__ uint32_t f2tf32(float f) {
    uint32_t r;
    asm("cvt.rna.tf32.f32 %0, %1;" : "=r"(r) : "f"(f));
    return r;
}
__device__ __forceinline__ float ex2(float x) {
    float y;
    asm("ex2.approx.f32 %0, %1;" : "=f"(y) : "f"(x));
    return y;
}
__device__ __forceinline__ void mma8(float* d, const uint32_t* a, const uint32_t* b) {
    asm volatile(
        "mma.sync.aligned.m16n8k8.row.col.f32.tf32.tf32.f32 "
        "{%0,%1,%2,%3}, {%4,%5,%6,%7}, {%8,%9}, {%0,%1,%2,%3};"
        : "+f"(d[0]), "+f"(d[1]), "+f"(d[2]), "+f"(d[3])
        : "r"(a[0]), "r"(a[1]), "r"(a[2]), "r"(a[3]), "r"(b[0]), "r"(b[1]));
}
__device__ __forceinline__ void cpa16(uint32_t dst, const float* src) {
    asm volatile("cp.async.cg.shared.global [%0], [%1], 16;"
                 :: "r"(dst), "l"(src) : "memory");
}

// copy one 64x64 K tile + V tile (raw fp32) into smem buffers; 8+8 chunks/thread
__device__ __forceinline__ void issue_tile(uint32_t kdst, uint32_t vdst,
                                           const float* kbase, const float* vbase,
                                           int k0, int t) {
    #pragma unroll
    for (int i = 0; i < 8; i++) {
        int idx = t + i * NT, row = idx >> 4, c4 = idx & 15;
        size_t go = (size_t)(k0 + row) * (H * Dh) + (size_t)c4 * 4;
        uint32_t so = (uint32_t)(row * (PAD * 4) + c4 * 16);
        cpa16(kdst + so, kbase + go);
        cpa16(vdst + so, vbase + go);
    }
    asm volatile("cp.async.commit_group;" ::: "memory");
}

__global__ void __launch_bounds__(NT, 2)
fa_mma_kernel(const float* __restrict__ q, const float* __restrict__ k,
              const float* __restrict__ v, const int* __restrict__ causal_p,
              float* __restrict__ out)
{
    extern __shared__ float sm[];
    uint32_t smb;
    asm("{ .reg .u64 t; cvta.to.shared.u64 t, %1; cvt.u32.u64 %0, t; }"
        : "=r"(smb) : "l"(sm));
    float* Ps = sm + PS_OFF;

    const int t    = threadIdx.x;
    const int wid  = t >> 5;
    const int lane = t & 31;
    const int g    = lane >> 2;
    const int tg   = lane & 3;
    const int h    = blockIdx.x;
    const int qb   = (int)gridDim.y - 1 - (int)blockIdx.y;  // heavy tiles first
    const int causal = *causal_p;
    const int wb   = wid * 32;
    const float c  = 0.125f * 1.44269504088896340736f;      // D^-0.5 * log2(e)

    const float* kbase = k + (size_t)h * Dh;
    const float* vbase = v + (size_t)h * Dh;

    const int ktiles = causal ? 2 * (qb + 1) : (S_LEN / BN);

    // ---- prefetch tile 0 into buffer 0
    issue_tile(smb + K0_OFF * 4, smb + V0_OFF * 4, kbase, vbase, 0, t);

    // ---- stage Q (scale folded, rna tf32) into Ps, lift fragments to regs
    #pragma unroll
    for (int i = 0; i < 16; i++) {
        int idx = t + i * NT, row = idx >> 4, c4 = idx & 15;
        float4 f = ((const float4*)(q + (size_t)(qb * BM + row) * (H * Dh) + h * Dh))[c4];
        uint32_t* d = (uint32_t*)(Ps + row * PAD + c4 * 4);
        d[0] = f2tf32(f.x * c); d[1] = f2tf32(f.y * c);
        d[2] = f2tf32(f.z * c); d[3] = f2tf32(f.w * c);
    }
    __syncthreads();

    uint32_t qa[2][8][4];   // [mtile][ktile][frag] — rows are warp-private
    #pragma unroll
    for (int mt = 0; mt < 2; mt++) {
        int r0 = wb + mt * 16 + g;
        #pragma unroll
        for (int kt = 0; kt < 8; kt++) {
            qa[mt][kt][0] = __float_as_uint(Ps[r0 * PAD + kt * 8 + tg]);
            qa[mt][kt][1] = __float_as_uint(Ps[(r0 + 8) * PAD + kt * 8 + tg]);
            qa[mt][kt][2] = __float_as_uint(Ps[r0 * PAD + kt * 8 + tg + 4]);
            qa[mt][kt][3] = __float_as_uint(Ps[(r0 + 8) * PAD + kt * 8 + tg + 4]);
        }
    }

    float o[2][8][4];
    #pragma unroll
    for (int mt = 0; mt < 2; mt++)
        #pragma unroll
        for (int nt = 0; nt < 8; nt++)
            #pragma unroll
            for (int e = 0; e < 4; e++) o[mt][nt][e] = 0.0f;
    float mrow[4] = {-INFINITY, -INFINITY, -INFINITY, -INFINITY};
    float lrow[4] = {0.0f, 0.0f, 0.0f, 0.0f};

    for (int kb = 0; kb < ktiles; kb++) {
        const int k0 = kb * BN;
        const int cur = kb & 1;
        float* Ks = sm + K0_OFF + cur * TILE_F;
        float* Vs = sm + V0_OFF + cur * TILE_F;

        // (a) all warps done with buffer cur^1 (consumed in iter kb-1)
        __syncthreads();
        if (kb + 1 < ktiles)
            issue_tile(smb + (K0_OFF + (cur ^ 1) * TILE_F) * 4,
                       smb + (V0_OFF + (cur ^ 1) * TILE_F) * 4,
                       kbase, vbase, k0 + BN, t);
        else
            asm volatile("cp.async.commit_group;" ::: "memory");
        // tile kb complete (all but newest group)
        asm volatile("cp.async.wait_group 1;" ::: "memory");
        __syncthreads();   // (b) tile kb visible CTA-wide

        // ---- MMA1: S[32 x 64] = Q @ K^T (per warp)
        float s[2][8][4];
        #pragma unroll
        for (int mt = 0; mt < 2; mt++)
            #pragma unroll
            for (int nt = 0; nt < 8; nt++)
                #pragma unroll
                for (int e = 0; e < 4; e++) s[mt][nt][e] = 0.0f;

        #pragma unroll
        for (int kt = 0; kt < 8; kt++) {
            #pragma unroll
            for (int nt = 0; nt < 8; nt++) {
                uint32_t b[2];
                b[0] = *(const uint32_t*)(Ks + (nt * 8 + g) * PAD + kt * 8 + tg);
                b[1] = *(const uint32_t*)(Ks + (nt * 8 + g) * PAD + kt * 8 + tg + 4);
                mma8(s[0][nt], qa[0][kt], b);
                mma8(s[1][nt], qa[1][kt], b);
            }
        }

        // ---- causal mask (diagonal tiles only)
        if (causal && kb >= 2 * qb) {
            #pragma unroll
            for (int mt = 0; mt < 2; mt++) {
                int r0 = qb * BM + wb + mt * 16 + g;
                #pragma unroll
                for (int nt = 0; nt < 8; nt++) {
                    int col = k0 + nt * 8 + 2 * tg;
                    if (col     > r0)     s[mt][nt][0] = -INFINITY;
                    if (col + 1 > r0)     s[mt][nt][1] = -INFINITY;
                    if (col     > r0 + 8) s[mt][nt][2] = -INFINITY;
                    if (col + 1 > r0 + 8) s[mt][nt][3] = -INFINITY;
                }
            }
        }

        // ---- online softmax (4 rows/thread; quad owns a row)
        #pragma unroll
        for (int mt = 0; mt < 2; mt++) {
            #pragma unroll
            for (int hi = 0; hi < 2; hi++) {
                const int ri = mt * 2 + hi;
                float tm = -INFINITY;
                #pragma unroll
                for (int nt = 0; nt < 8; nt++)
                    tm = fmaxf(tm, fmaxf(s[mt][nt][hi * 2], s[mt][nt][hi * 2 + 1]));
                tm = fmaxf(tm, __shfl_xor_sync(0xffffffffu, tm, 1));
                tm = fmaxf(tm, __shfl_xor_sync(0xffffffffu, tm, 2));
                float nm   = fmaxf(mrow[ri], tm);
                float corr = ex2(mrow[ri] - nm);     // -inf first tile -> 0
                mrow[ri] = nm;
                float ls = 0.0f;
                #pragma unroll
                for (int nt = 0; nt < 8; nt++) {
                    float e0 = ex2(s[mt][nt][hi * 2]     - nm);
                    float e1 = ex2(s[mt][nt][hi * 2 + 1] - nm);
                    s[mt][nt][hi * 2]     = e0;
                    s[mt][nt][hi * 2 + 1] = e1;
                    ls += e0 + e1;
                    o[mt][nt][hi * 2]     *= corr;
                    o[mt][nt][hi * 2 + 1] *= corr;
                }
                lrow[ri] = lrow[ri] * corr + ls;
            }
        }

        // ---- P -> smem (raw fp32; HW truncates). warp-private rows
        #pragma unroll
        for (int mt = 0; mt < 2; mt++) {
            int r0 = wb + mt * 16 + g;
            #pragma unroll
            for (int nt = 0; nt < 8; nt++) {
                float2* d0 = (float2*)(Ps + r0 * PAD + nt * 8 + 2 * tg);
                *d0 = make_float2(s[mt][nt][0], s[mt][nt][1]);
                float2* d1 = (float2*)(Ps + (r0 + 8) * PAD + nt * 8 + 2 * tg);
                *d1 = make_float2(s[mt][nt][2], s[mt][nt][3]);
            }
        }
        __syncwarp();

        // ---- MMA2: O += P @ V
        #pragma unroll
        for (int kt = 0; kt < 8; kt++) {
            uint32_t pa[2][4];
            #pragma unroll
            for (int mt = 0; mt < 2; mt++) {
                int r0 = wb + mt * 16 + g;
                pa[mt][0] = __float_as_uint(Ps[r0 * PAD + kt * 8 + tg]);
                pa[mt][1] = __float_as_uint(Ps[(r0 + 8) * PAD + kt * 8 + tg]);
                pa[mt][2] = __float_as_uint(Ps[r0 * PAD + kt * 8 + tg + 4]);
                pa[mt][3] = __float_as_uint(Ps[(r0 + 8) * PAD + kt * 8 + tg + 4]);
            }
            #pragma unroll
            for (int nt = 0; nt < 8; nt++) {
                uint32_t b[2];
                b[0] = *(const uint32_t*)(Vs + (kt * 8 + tg) * PAD + nt * 8 + g);
                b[1] = *(const uint32_t*)(Vs + (kt * 8 + tg + 4) * PAD + nt * 8 + g);
                mma8(o[0][nt], pa[0], b);
                mma8(o[1][nt], pa[1], b);
            }
        }
    }

    // ---- finalize: row-sum across quad, normalize, store
    #pragma unroll
    for (int ri = 0; ri < 4; ri++) {
        lrow[ri] += __shfl_xor_sync(0xffffffffu, lrow[ri], 1);
        lrow[ri] += __shfl_xor_sync(0xffffffffu, lrow[ri], 2);
    }
    #pragma unroll
    for (int mt = 0; mt < 2; mt++) {
        #pragma unroll
        for (int hi = 0; hi < 2; hi++) {
            const int ri = mt * 2 + hi;
            const float inv = 1.0f / lrow[ri];
            const int rg = qb * BM + wb + mt * 16 + g + hi * 8;
            float* op = out + (size_t)rg * (H * Dh) + (size_t)h * Dh;
            #pragma unroll
            for (int nt = 0; nt < 8; nt++) {
                float2 f2;
                f2.x = o[mt][nt][hi * 2]     * inv;
                f2.y = o[mt][nt][hi * 2 + 1] * inv;
                *(float2*)(op + nt * 8 + 2 * tg) = f2;
            }
        }
    }
}

extern "C" void kernel_launch(void* const* d_in, const int* in_sizes, int n_in,
                              void* d_out, int out_size)
{
    const float* q = (const float*)d_in[0];
    const float* k = (const float*)d_in[1];
    const float* v = (const float*)d_in[2];
    const int* causal = (const int*)d_in[3];
    float* out = (float*)d_out;

    cudaFuncSetAttribute(fa_mma_kernel,
                         cudaFuncAttributeMaxDynamicSharedMemorySize, SMEM_BYTES);
    dim3 grid(H, S_LEN / BM);   // (16, 32)
    fa_mma_kernel<<<grid, NT, SMEM_BYTES>>>(q, k, v, causal, out);
}